// round 16
// baseline (speedup 1.0000x reference)
#include <cuda_runtime.h>
#include <cuda_bf16.h>
#include <cstdint>
#include <math.h>

#define T_TOK 8192
#define DIM   1024
#define HID   4096
#define NE    8
#define KCH   32   // macro-chunk: two k16 sub-tiles per stage
#define PADA  12   // A tile u32 row stride (48B)
#define PADB  36   // B tile u32 row stride (144B)
#define SPLITK 4   // gemm2 split-K factor
#define KSEG  (HID / SPLITK)

// ------------------------- scratch: pre-split bf16 operands -------------------------
__device__ __nv_bfloat16 g_xh[(size_t)T_TOK * DIM],  g_xl[(size_t)T_TOK * DIM];
__device__ __nv_bfloat16 g_w1h[(size_t)NE * DIM * HID], g_w1l[(size_t)NE * DIM * HID]; // [E][k=D][n=H]
__device__ __nv_bfloat16 g_w3h[(size_t)NE * DIM * HID], g_w3l[(size_t)NE * DIM * HID]; // [E][k=D][n=H]
__device__ __nv_bfloat16 g_w2h[(size_t)NE * HID * DIM], g_w2l[(size_t)NE * HID * DIM]; // [E][k=H][n=D]
__device__ __nv_bfloat16 g_Hh[(size_t)2 * T_TOK * HID], g_Hl[(size_t)2 * T_TOK * HID]; // slot-major
__device__ int   g_entry[NE * T_TOK];
__device__ float g_topw[2 * T_TOK];
__device__ int   g_cnt[NE];
__device__ float g_usage[NE];

// ------------------------- helpers -------------------------
__device__ __forceinline__ uint32_t smem_to_u32(const void* p) {
    uint32_t a;
    asm("{ .reg .u64 t; cvta.to.shared.u64 t, %1; cvt.u32.u64 %0, t; }" : "=r"(a) : "l"(p));
    return a;
}
#define CP16(dst, src) asm volatile("cp.async.cg.shared.global [%0], [%1], 16;" :: "r"(dst), "l"(src))
#define CP_COMMIT() asm volatile("cp.async.commit_group;" ::: "memory")
#define CP_WAIT0()  asm volatile("cp.async.wait_group 0;" ::: "memory")

__device__ __forceinline__ void ldm_x4(uint32_t* f, uint32_t addr) {
    asm volatile("ldmatrix.sync.aligned.m8n8.x4.shared.b16 {%0,%1,%2,%3}, [%4];"
        : "=r"(f[0]), "=r"(f[1]), "=r"(f[2]), "=r"(f[3]) : "r"(addr));
}
__device__ __forceinline__ void ldm_x4_t(uint32_t* f, uint32_t addr) {
    asm volatile("ldmatrix.sync.aligned.m8n8.x4.trans.shared.b16 {%0,%1,%2,%3}, [%4];"
        : "=r"(f[0]), "=r"(f[1]), "=r"(f[2]), "=r"(f[3]) : "r"(addr));
}
__device__ __forceinline__ void mma16816(float* c, const uint32_t* a, const uint32_t* b) {
    asm volatile(
        "mma.sync.aligned.m16n8k16.row.col.f32.bf16.bf16.f32 "
        "{%0,%1,%2,%3}, {%4,%5,%6,%7}, {%8,%9}, {%0,%1,%2,%3};"
        : "+f"(c[0]), "+f"(c[1]), "+f"(c[2]), "+f"(c[3])
        : "r"(a[0]), "r"(a[1]), "r"(a[2]), "r"(a[3]), "r"(b[0]), "r"(b[1]));
}
__device__ __forceinline__ uint32_t pack_bf2(__nv_bfloat16 a, __nv_bfloat16 b) {
    return (uint32_t)__bfloat16_as_ushort(a) | ((uint32_t)__bfloat16_as_ushort(b) << 16);
}
__device__ __forceinline__ void split2(float f0, float f1, uint32_t& hi, uint32_t& lo) {
    __nv_bfloat16 h0 = __float2bfloat16(f0);
    __nv_bfloat16 h1 = __float2bfloat16(f1);
    __nv_bfloat16 l0 = __float2bfloat16(f0 - __bfloat162float(h0));
    __nv_bfloat16 l1 = __float2bfloat16(f1 - __bfloat162float(h1));
    hi = pack_bf2(h0, h1);
    lo = pack_bf2(l0, l1);
}
__device__ __forceinline__ uint32_t lane_offA(int lane) {
    return (uint32_t)((((lane & 7) + ((lane >> 3) & 1) * 8)) * (PADA * 4) + (lane >> 4) * 16);
}
__device__ __forceinline__ uint32_t lane_offB(int lane) {
    return (uint32_t)((((lane & 7) + ((lane >> 3) & 1) * 8)) * (PADB * 4) + (lane >> 4) * 16);
}

// per-k16 tile sizes (u32)
#define A_ST   (128 * PADA)     // 1536
#define B_ST   (16 * PADB)      // 576
#define SMEM13_U32 (8 * A_ST + 16 * B_ST)
#define SMEM13_BYTES (SMEM13_U32 * 4)       // 86016
#define SMEM2_U32 (8 * A_ST + 8 * B_ST)
#define SMEM2_BYTES (SMEM2_U32 * 4)         // 67584

// ------------------------- init / router / aux -------------------------
__global__ void init_kernel(float* out, int out_elems4) {
    int i = blockIdx.x * blockDim.x + threadIdx.x;
    if (i < out_elems4) ((float4*)out)[i] = make_float4(0.f, 0.f, 0.f, 0.f);
    if (i < NE) { g_cnt[i] = 0; g_usage[i] = 0.f; }
}

__global__ void router_kernel(const float* __restrict__ x, const float* __restrict__ gw) {
    int warp = (blockIdx.x * blockDim.x + threadIdx.x) >> 5;
    int lane = threadIdx.x & 31;
    if (warp >= T_TOK) return;
    const float* xr = x + (size_t)warp * DIM;
    float acc[NE];
#pragma unroll
    for (int e = 0; e < NE; e++) acc[e] = 0.f;
    for (int d = lane; d < DIM; d += 32) {
        float xv = xr[d];
#pragma unroll
        for (int e = 0; e < NE; e++) acc[e] = fmaf(xv, gw[d * NE + e], acc[e]);
    }
#pragma unroll
    for (int off = 16; off; off >>= 1)
#pragma unroll
        for (int e = 0; e < NE; e++) acc[e] += __shfl_xor_sync(0xffffffffu, acc[e], off);
    if (lane == 0) {
        float m = acc[0];
#pragma unroll
        for (int e = 1; e < NE; e++) m = fmaxf(m, acc[e]);
        float Z = 0.f, p[NE];
#pragma unroll
        for (int e = 0; e < NE; e++) { p[e] = expf(acc[e] - m); Z += p[e]; }
        float invZ = 1.f / Z;
#pragma unroll
        for (int e = 0; e < NE; e++) atomicAdd(&g_usage[e], p[e] * invZ);
        int i0 = 0;
#pragma unroll
        for (int e = 1; e < NE; e++) if (acc[e] > acc[i0]) i0 = e;
        int i1 = (i0 == 0) ? 1 : 0;
#pragma unroll
        for (int e = 0; e < NE; e++) if (e != i0 && acc[e] > acc[i1]) i1 = e;
        float e1 = expf(acc[i1] - acc[i0]);
        float w0 = 1.f / (1.f + e1);
        g_topw[2 * warp]     = w0;
        g_topw[2 * warp + 1] = e1 * w0;
        int p0 = atomicAdd(&g_cnt[i0], 1);
        g_entry[i0 * T_TOK + p0] = warp * 2;
        int p1 = atomicAdd(&g_cnt[i1], 1);
        g_entry[i1 * T_TOK + p1] = warp * 2 + 1;
    }
}

__global__ void aux_kernel(float* out, int has_aux) {
    if (!has_aux) return;
    float s = 0.f;
#pragma unroll
    for (int e = 0; e < NE; e++) { float u = g_usage[e] / (float)T_TOK; s += u * u; }
    out[(size_t)T_TOK * DIM] = (float)NE * s;
}

// ------------------------- elementwise fp32 -> bf16 hi/lo split (8 elems/thread) -------------------------
__global__ void conv_split_kernel(const float4* __restrict__ src, int which, int n8) {
    int i = blockIdx.x * blockDim.x + threadIdx.x;
    if (i >= n8) return;
    uint4* dh; uint4* dl;
    switch (which) {
        case 0:  dh = (uint4*)g_xh;  dl = (uint4*)g_xl;  break;
        case 1:  dh = (uint4*)g_w1h; dl = (uint4*)g_w1l; break;
        case 2:  dh = (uint4*)g_w3h; dl = (uint4*)g_w3l; break;
        default: dh = (uint4*)g_w2h; dl = (uint4*)g_w2l; break;
    }
    float4 v0 = src[2 * i], v1 = src[2 * i + 1];
    uint4 h, l;
    split2(v0.x, v0.y, h.x, l.x);
    split2(v0.z, v0.w, h.y, l.y);
    split2(v1.x, v1.y, h.z, l.z);
    split2(v1.z, v1.w, h.w, l.w);
    dh[i] = h;
    dl[i] = l;
}

// ------------------------- GEMM 1&3 fused over experts -------------------------
// 2-stage, macro-chunk KCH=32 = two k16 sub-tiles per stage (R15-proven).
#define NCH13 (DIM / KCH)

__global__ __launch_bounds__(256, 2)
void gemm13_mma_kernel()
{
    extern __shared__ uint32_t dynsm[];
    const uint32_t smb = smem_to_u32(dynsm);
    const uint32_t oAh = 0, oAl = 4 * A_ST;
    const uint32_t oB1h = 8 * A_ST, oB1l = 8 * A_ST + 4 * B_ST;
    const uint32_t oB3h = 8 * A_ST + 8 * B_ST, oB3l = 8 * A_ST + 12 * B_ST;

    int e = blockIdx.z;
    int n = g_cnt[e];
    int rowBase = blockIdx.x * 128;
    if (rowBase >= n) return;
    int colBase = blockIdx.y * 64;
    int tid = threadIdx.x, wid = tid >> 5, lane = tid & 31;
    int m0 = (wid & 3) * 32, n0 = (wid >> 2) * 32;
    int grp = lane >> 2, t4 = lane & 3;

    int arow = tid >> 1, ahalf = tid & 1;
    int rA = rowBase + arow;
    int slotA = (rA < n) ? g_entry[e * T_TOK + rA] : 0;
    const __nv_bfloat16* srcAh = g_xh + (size_t)(slotA >> 1) * DIM + ahalf * 8;
    const __nv_bfloat16* srcAl = g_xl + (size_t)(slotA >> 1) * DIM + ahalf * 8;

    int bidx = tid & 127, bk = bidx >> 3, bseg = bidx & 7;
    int isB3 = tid >> 7;
    const size_t ebW = (size_t)e * DIM * HID;
    const __nv_bfloat16* srcBh = (isB3 ? g_w3h : g_w1h) + ebW + (size_t)bk * HID + colBase + bseg * 8;
    const __nv_bfloat16* srcBl = (isB3 ? g_w3l : g_w1l) + ebW + (size_t)bk * HID + colBase + bseg * 8;

    uint32_t dAh[2], dAl[2], dBh[2], dBl[2];
#pragma unroll
    for (int st = 0; st < 2; st++) {
        dAh[st] = smb + (oAh + st * 2 * A_ST) * 4 + arow * (PADA * 4) + ahalf * 16;
        dAl[st] = smb + (oAl + st * 2 * A_ST) * 4 + arow * (PADA * 4) + ahalf * 16;
        uint32_t obh = isB3 ? oB3h : oB1h, obl = isB3 ? oB3l : oB1l;
        dBh[st] = smb + (obh + st * 2 * B_ST) * 4 + bk * (PADB * 4) + bseg * 16;
        dBl[st] = smb + (obl + st * 2 * B_ST) * 4 + bk * (PADB * 4) + bseg * 16;
    }

    auto issue = [&](int st) {
#pragma unroll
        for (int sub = 0; sub < 2; sub++) {
            CP16(dAh[st] + sub * A_ST * 4, srcAh + sub * 16);
            CP16(dAl[st] + sub * A_ST * 4, srcAl + sub * 16);
            CP16(dBh[st] + sub * B_ST * 4, srcBh + (size_t)sub * 16 * HID);
            CP16(dBl[st] + sub * B_ST * 4, srcBl + (size_t)sub * 16 * HID);
        }
        srcAh += KCH; srcAl += KCH;
        srcBh += (size_t)KCH * HID; srcBl += (size_t)KCH * HID;
    };

    uint32_t loA = lane_offA(lane), loB = lane_offB(lane);
    uint32_t bAH[2], bAL[2], b1H[2], b1L[2], b3H[2], b3L[2];
#pragma unroll
    for (int st = 0; st < 2; st++) {
        bAH[st] = smb + (oAh + st * 2 * A_ST) * 4 + loA + (uint32_t)m0 * (PADA * 4);
        bAL[st] = smb + (oAl + st * 2 * A_ST) * 4 + loA + (uint32_t)m0 * (PADA * 4);
        b1H[st] = smb + (oB1h + st * 2 * B_ST) * 4 + loB + (uint32_t)n0 * 2;
        b1L[st] = smb + (oB1l + st * 2 * B_ST) * 4 + loB + (uint32_t)n0 * 2;
        b3H[st] = smb + (oB3h + st * 2 * B_ST) * 4 + loB + (uint32_t)n0 * 2;
        b3L[st] = smb + (oB3l + st * 2 * B_ST) * 4 + loB + (uint32_t)n0 * 2;
    }

    float c1[2][4][4], c3[2][4][4];
#pragma unroll
    for (int mt = 0; mt < 2; mt++)
#pragma unroll
        for (int j = 0; j < 4; j++)
#pragma unroll
            for (int q = 0; q < 4; q++) { c1[mt][j][q] = 0.f; c3[mt][j][q] = 0.f; }

    issue(0); CP_COMMIT();

    for (int c = 0; c < NCH13; c++) {
        int st = c & 1;
        CP_WAIT0();
        __syncthreads();
        if (c + 1 < NCH13) { issue(st ^ 1); CP_COMMIT(); }
#pragma unroll
        for (int ks = 0; ks < 2; ks++) {
            uint32_t kA = ks * A_ST * 4, kB = ks * B_ST * 4;
            uint32_t ah[2][4], al[2][4];
#pragma unroll
            for (int mt = 0; mt < 2; mt++) {
                ldm_x4(ah[mt], bAH[st] + kA + mt * 16 * (PADA * 4));
                ldm_x4(al[mt], bAL[st] + kA + mt * 16 * (PADA * 4));
            }
#pragma unroll
            for (int nh = 0; nh < 2; nh++) {
                uint32_t f1h[4], f1l[4], f3h[4], f3l[4];
                ldm_x4_t(f1h, b1H[st] + kB + nh * 32);
                ldm_x4_t(f1l, b1L[st] + kB + nh * 32);
                ldm_x4_t(f3h, b3H[st] + kB + nh * 32);
                ldm_x4_t(f3l, b3L[st] + kB + nh * 32);
#pragma unroll
                for (int j = 0; j < 2; j++) {
                    int nt = nh * 2 + j;
                    uint32_t b1hF[2] = { f1h[2 * j], f1h[2 * j + 1] };
                    uint32_t b1lF[2] = { f1l[2 * j], f1l[2 * j + 1] };
                    uint32_t b3hF[2] = { f3h[2 * j], f3h[2 * j + 1] };
                    uint32_t b3lF[2] = { f3l[2 * j], f3l[2 * j + 1] };
#pragma unroll
                    for (int mt = 0; mt < 2; mt++) {
                        mma16816(c1[mt][nt], ah[mt], b1hF);
                        mma16816(c1[mt][nt], ah[mt], b1lF);
                        mma16816(c1[mt][nt], al[mt], b1hF);
                        mma16816(c3[mt][nt], ah[mt], b3hF);
                        mma16816(c3[mt][nt], ah[mt], b3lF);
                        mma16816(c3[mt][nt], al[mt], b3hF);
                    }
                }
            }
        }
    }

    // epilogue: h = silu(c1) * c3 -> bf16 hi/lo at g_Hh/g_Hl[slot]
#pragma unroll
    for (int mt = 0; mt < 2; mt++)
#pragma unroll
        for (int hf = 0; hf < 2; hf++) {
            int rr = m0 + mt * 16 + grp + hf * 8;
            int r = rowBase + rr;
            if (r < n) {
                int slot = g_entry[e * T_TOK + r];
#pragma unroll
                for (int nt = 0; nt < 4; nt++) {
                    int col = colBase + n0 + nt * 8 + t4 * 2;
                    float a0 = c1[mt][nt][hf * 2 + 0], b0 = c3[mt][nt][hf * 2 + 0];
                    float a1 = c1[mt][nt][hf * 2 + 1], b1 = c3[mt][nt][hf * 2 + 1];
                    float h0 = (a0 / (1.f + expf(-a0))) * b0;
                    float h1 = (a1 / (1.f + expf(-a1))) * b1;
                    uint32_t hh, ll;
                    split2(h0, h1, hh, ll);
                    *(uint32_t*)(g_Hh + (size_t)slot * HID + col) = hh;
                    *(uint32_t*)(g_Hl + (size_t)slot * HID + col) = ll;
                }
            }
        }
}

// ------------------------- GEMM 2 fused over experts, split-K -------------------------
// blockIdx.x = rowBlk * SPLITK + sk. Each CTA sums K range [sk*KSEG, (sk+1)*KSEG).
#define NCH2 (KSEG / KCH)

__global__ __launch_bounds__(256, 2)
void gemm2_mma_kernel(float* __restrict__ out)
{
    extern __shared__ uint32_t dynsm[];
    const uint32_t smb = smem_to_u32(dynsm);
    const uint32_t oAh = 0, oAl = 4 * A_ST;
    const uint32_t oBh = 8 * A_ST, oBl = 8 * A_ST + 4 * B_ST;
    __shared__ int sSlot[128];

    int e = blockIdx.z;
    int n = g_cnt[e];
    int rowBlk = blockIdx.x / SPLITK;
    int sk = blockIdx.x % SPLITK;
    int rowBase = rowBlk * 128;
    if (rowBase >= n) return;
    int colBase = blockIdx.y * 64;
    int kOff = sk * KSEG;
    int tid = threadIdx.x, wid = tid >> 5, lane = tid & 31;
    int m0 = (wid & 3) * 32, n0 = (wid >> 2) * 32;
    int grp = lane >> 2, t4 = lane & 3;

    if (tid < 128) {
        int r = rowBase + tid;
        sSlot[tid] = (r < n) ? g_entry[e * T_TOK + r] : 0;
    }
    __syncthreads();

    int arow = tid >> 1, ahalf = tid & 1;
    const __nv_bfloat16* srcAh = g_Hh + (size_t)sSlot[arow] * HID + kOff + ahalf * 8;
    const __nv_bfloat16* srcAl = g_Hl + (size_t)sSlot[arow] * HID + kOff + ahalf * 8;

    int bidx = tid & 127, bk = bidx >> 3, bseg = bidx & 7;
    int half2 = tid >> 7;
    const size_t ebW = (size_t)e * HID * DIM;
    const __nv_bfloat16* srcBh = g_w2h + ebW + (size_t)(kOff + bk) * DIM + colBase + bseg * 8;
    const __nv_bfloat16* srcBl = g_w2l + ebW + (size_t)(kOff + bk) * DIM + colBase + bseg * 8;

    uint32_t dAh[2], dAl[2], dBh[2], dBl[2];
#pragma unroll
    for (int st = 0; st < 2; st++) {
        dAh[st] = smb + (oAh + st * 2 * A_ST) * 4 + arow * (PADA * 4) + ahalf * 16;
        dAl[st] = smb + (oAl + st * 2 * A_ST) * 4 + arow * (PADA * 4) + ahalf * 16;
        dBh[st] = smb + (oBh + st * 2 * B_ST) * 4 + bk * (PADB * 4) + bseg * 16;
        dBl[st] = smb + (oBl + st * 2 * B_ST) * 4 + bk * (PADB * 4) + bseg * 16;
    }

    auto issue = [&](int st) {
#pragma unroll
        for (int sub = 0; sub < 2; sub++) {
            CP16(dAh[st] + sub * A_ST * 4, srcAh + sub * 16);
            CP16(dAl[st] + sub * A_ST * 4, srcAl + sub * 16);
            if (!half2) {
                CP16(dBh[st] + sub * B_ST * 4, srcBh + (size_t)sub * 16 * DIM);
                CP16(dBl[st] + sub * B_ST * 4, srcBl + (size_t)sub * 16 * DIM);
            }
        }
        srcAh += KCH; srcAl += KCH;
        srcBh += (size_t)KCH * DIM; srcBl += (size_t)KCH * DIM;
    };

    uint32_t loA = lane_offA(lane), loB = lane_offB(lane);
    uint32_t bAH[2], bAL[2], bBH[2], bBL[2];
#pragma unroll
    for (int st = 0; st < 2; st++) {
        bAH[st] = smb + (oAh + st * 2 * A_ST) * 4 + loA + (uint32_t)m0 * (PADA * 4);
        bAL[st] = smb + (oAl + st * 2 * A_ST) * 4 + loA + (uint32_t)m0 * (PADA * 4);
        bBH[st] = smb + (oBh + st * 2 * B_ST) * 4 + loB + (uint32_t)n0 * 2;
        bBL[st] = smb + (oBl + st * 2 * B_ST) * 4 + loB + (uint32_t)n0 * 2;
    }

    float acc[2][4][4];
#pragma unroll
    for (int mt = 0; mt < 2; mt++)
#pragma unroll
        for (int j = 0; j < 4; j++)
#pragma unroll
            for (int q = 0; q < 4; q++) acc[mt][j][q] = 0.f;

    issue(0); CP_COMMIT();

    for (int c = 0; c < NCH2; c++) {
        int st = c & 1;
        CP_WAIT0();
        __syncthreads();
        if (c + 1 < NCH2) { issue(st ^ 1); CP_COMMIT(); }
#pragma unroll
        for (int ks = 0; ks < 2; ks++) {
            uint32_t kA = ks * A_ST * 4, kB = ks * B_ST * 4;
            uint32_t ah[2][4], al[2][4];
#pragma unroll
            for (int mt = 0; mt < 2; mt++) {
                ldm_x4(ah[mt], bAH[st] + kA + mt * 16 * (PADA * 4));
                ldm_x4(al[mt], bAL[st] + kA + mt * 16 * (PADA * 4));
            }
#pragma unroll
            for (int nh = 0; nh < 2; nh++) {
                uint32_t fh[4], fl[4];
                ldm_x4_t(fh, bBH[st] + kB + nh * 32);
                ldm_x4_t(fl, bBL[st] + kB + nh * 32);
#pragma unroll
                for (int j = 0; j < 2; j++) {
                    int nt = nh * 2 + j;
                    uint32_t bhF[2] = { fh[2 * j], fh[2 * j + 1] };
                    uint32_t blF[2] = { fl[2 * j], fl[2 * j + 1] };
#pragma unroll
                    for (int mt = 0; mt < 2; mt++) {
                        mma16816(acc[mt][nt], ah[mt], bhF);
                        mma16816(acc[mt][nt], ah[mt], blF);
                        mma16816(acc[mt][nt], al[mt], bhF);
                    }
                }
            }
        }
    }

    // epilogue: atomic combine into out (split-K partials accumulate)
#pragma unroll
    for (int mt = 0; mt < 2; mt++)
#pragma unroll
        for (int hf = 0; hf < 2; hf++) {
            int rr = m0 + mt * 16 + grp + hf * 8;
            int r = rowBase + rr;
            if (r < n) {
                int slot = sSlot[rr];
                float wgt = g_topw[slot];
                float* op = out + (size_t)(slot >> 1) * DIM;
#pragma unroll
                for (int nt = 0; nt < 4; nt++) {
                    int col = colBase + n0 + nt * 8 + t4 * 2;
                    atomicAdd(op + col,     wgt * acc[mt][nt][hf * 2 + 0]);
                    atomicAdd(op + col + 1, wgt * acc[mt][nt][hf * 2 + 1]);
                }
            }
        }
}

// ------------------------- launch -------------------------
extern "C" void kernel_launch(void* const* d_in, const int* in_sizes, int n_in,
                              void* d_out, int out_size) {
    const float* x  = (const float*)d_in[0];
    const float* gw = (const float*)d_in[1];
    const float* w1 = (const float*)d_in[2];
    const float* w2 = (const float*)d_in[3];
    const float* w3 = (const float*)d_in[4];
    float* out = (float*)d_out;

    const int out_elems = T_TOK * DIM;
    const int out_elems4 = out_elems / 4;
    const int xn8 = T_TOK * DIM / 8;
    const int wn8 = NE * DIM * HID / 8;

    cudaFuncSetAttribute(gemm13_mma_kernel, cudaFuncAttributeMaxDynamicSharedMemorySize, SMEM13_BYTES);
    cudaFuncSetAttribute(gemm2_mma_kernel,  cudaFuncAttributeMaxDynamicSharedMemorySize, SMEM2_BYTES);

    init_kernel<<<(out_elems4 + 255) / 256, 256>>>(out, out_elems4);
    router_kernel<<<T_TOK / 8, 256>>>(x, gw);
    aux_kernel<<<1, 1>>>(out, (out_size > out_elems) ? 1 : 0);

    conv_split_kernel<<<(xn8 + 255) / 256, 256>>>((const float4*)x, 0, xn8);
    conv_split_kernel<<<(wn8 + 255) / 256, 256>>>((const float4*)w1, 1, wn8);
    conv_split_kernel<<<(wn8 + 255) / 256, 256>>>((const float4*)w3, 2, wn8);
    conv_split_kernel<<<(wn8 + 255) / 256, 256>>>((const float4*)w2, 3, wn8);

    gemm13_mma_kernel<<<dim3(T_TOK / 128, HID / 64, NE), 256, SMEM13_BYTES>>>();
    gemm2_mma_kernel<<<dim3((T_TOK / 128) * SPLITK, DIM / 64, NE), 256, SMEM2_BYTES>>>(out);
}

// round 17
// speedup vs baseline: 1.4095x; 1.4095x over previous
#include <cuda_runtime.h>
#include <cuda_fp16.h>
#include <cstdint>
#include <math.h>

#define T_TOK 8192
#define DIM   1024
#define HID   4096
#define NE    8
#define KCH   32   // macro-chunk: two k16 sub-tiles per stage
#define PADA  12   // A tile u32 row stride (48B)
#define PADB  36   // B tile u32 row stride (144B)

// ------------------------- scratch: fp16 operands -------------------------
__device__ __half g_xh[(size_t)T_TOK * DIM],  g_xl[(size_t)T_TOK * DIM];   // x hi/lo
__device__ __half g_w1[(size_t)NE * DIM * HID];   // [E][k=D][n=H] single fp16
__device__ __half g_w3[(size_t)NE * DIM * HID];
__device__ __half g_w2[(size_t)NE * HID * DIM];   // [E][k=H][n=D]
__device__ __half g_Hh[(size_t)2 * T_TOK * HID], g_Hl[(size_t)2 * T_TOK * HID]; // slot-major hi/lo
__device__ int   g_entry[NE * T_TOK];
__device__ float g_topw[2 * T_TOK];
__device__ int   g_cnt[NE];
__device__ float g_usage[NE];

// ------------------------- helpers -------------------------
__device__ __forceinline__ uint32_t smem_to_u32(const void* p) {
    uint32_t a;
    asm("{ .reg .u64 t; cvta.to.shared.u64 t, %1; cvt.u32.u64 %0, t; }" : "=r"(a) : "l"(p));
    return a;
}
#define CP16(dst, src) asm volatile("cp.async.cg.shared.global [%0], [%1], 16;" :: "r"(dst), "l"(src))
#define CP_COMMIT() asm volatile("cp.async.commit_group;" ::: "memory")
#define CP_WAIT0()  asm volatile("cp.async.wait_group 0;" ::: "memory")

__device__ __forceinline__ void ldm_x4(uint32_t* f, uint32_t addr) {
    asm volatile("ldmatrix.sync.aligned.m8n8.x4.shared.b16 {%0,%1,%2,%3}, [%4];"
        : "=r"(f[0]), "=r"(f[1]), "=r"(f[2]), "=r"(f[3]) : "r"(addr));
}
__device__ __forceinline__ void ldm_x4_t(uint32_t* f, uint32_t addr) {
    asm volatile("ldmatrix.sync.aligned.m8n8.x4.trans.shared.b16 {%0,%1,%2,%3}, [%4];"
        : "=r"(f[0]), "=r"(f[1]), "=r"(f[2]), "=r"(f[3]) : "r"(addr));
}
__device__ __forceinline__ void mma16816(float* c, const uint32_t* a, const uint32_t* b) {
    asm volatile(
        "mma.sync.aligned.m16n8k16.row.col.f32.f16.f16.f32 "
        "{%0,%1,%2,%3}, {%4,%5,%6,%7}, {%8,%9}, {%0,%1,%2,%3};"
        : "+f"(c[0]), "+f"(c[1]), "+f"(c[2]), "+f"(c[3])
        : "r"(a[0]), "r"(a[1]), "r"(a[2]), "r"(a[3]), "r"(b[0]), "r"(b[1]));
}
__device__ __forceinline__ uint32_t pack_h2(__half a, __half b) {
    return (uint32_t)__half_as_ushort(a) | ((uint32_t)__half_as_ushort(b) << 16);
}
// fp32 -> fp16 hi + lo (hi+lo accurate to ~2^-22)
__device__ __forceinline__ void split2h(float f0, float f1, uint32_t& hi, uint32_t& lo) {
    __half h0 = __float2half_rn(f0);
    __half h1 = __float2half_rn(f1);
    __half l0 = __float2half_rn(f0 - __half2float(h0));
    __half l1 = __float2half_rn(f1 - __half2float(h1));
    hi = pack_h2(h0, h1);
    lo = pack_h2(l0, l1);
}
__device__ __forceinline__ uint32_t lane_offA(int lane) {
    return (uint32_t)((((lane & 7) + ((lane >> 3) & 1) * 8)) * (PADA * 4) + (lane >> 4) * 16);
}
__device__ __forceinline__ uint32_t lane_offB(int lane) {
    return (uint32_t)((((lane & 7) + ((lane >> 3) & 1) * 8)) * (PADB * 4) + (lane >> 4) * 16);
}

// per-k16 tile sizes (u32)
#define A_ST   (128 * PADA)     // 1536
#define B_ST   (16 * PADB)      // 576
// gemm13: A hi/lo (2 stage x 2 sub x 2) + B1,B3 single (2 stage x 2 sub x 2 matrices)
#define SMEM13_U32 (8 * A_ST + 8 * B_ST)    // 16896
#define SMEM13_BYTES (SMEM13_U32 * 4)       // 67584
#define SMEM2_U32 (8 * A_ST + 4 * B_ST)     // 14592
#define SMEM2_BYTES (SMEM2_U32 * 4)         // 58368

// ------------------------- init / router / aux -------------------------
__global__ void init_kernel(float* out, int out_elems4) {
    int i = blockIdx.x * blockDim.x + threadIdx.x;
    if (i < out_elems4) ((float4*)out)[i] = make_float4(0.f, 0.f, 0.f, 0.f);
    if (i < NE) { g_cnt[i] = 0; g_usage[i] = 0.f; }
}

__global__ void router_kernel(const float* __restrict__ x, const float* __restrict__ gw) {
    int warp = (blockIdx.x * blockDim.x + threadIdx.x) >> 5;
    int lane = threadIdx.x & 31;
    if (warp >= T_TOK) return;
    const float* xr = x + (size_t)warp * DIM;
    float acc[NE];
#pragma unroll
    for (int e = 0; e < NE; e++) acc[e] = 0.f;
    for (int d = lane; d < DIM; d += 32) {
        float xv = xr[d];
#pragma unroll
        for (int e = 0; e < NE; e++) acc[e] = fmaf(xv, gw[d * NE + e], acc[e]);
    }
#pragma unroll
    for (int off = 16; off; off >>= 1)
#pragma unroll
        for (int e = 0; e < NE; e++) acc[e] += __shfl_xor_sync(0xffffffffu, acc[e], off);
    if (lane == 0) {
        float m = acc[0];
#pragma unroll
        for (int e = 1; e < NE; e++) m = fmaxf(m, acc[e]);
        float Z = 0.f, p[NE];
#pragma unroll
        for (int e = 0; e < NE; e++) { p[e] = expf(acc[e] - m); Z += p[e]; }
        float invZ = 1.f / Z;
#pragma unroll
        for (int e = 0; e < NE; e++) atomicAdd(&g_usage[e], p[e] * invZ);
        int i0 = 0;
#pragma unroll
        for (int e = 1; e < NE; e++) if (acc[e] > acc[i0]) i0 = e;
        int i1 = (i0 == 0) ? 1 : 0;
#pragma unroll
        for (int e = 0; e < NE; e++) if (e != i0 && acc[e] > acc[i1]) i1 = e;
        float e1 = expf(acc[i1] - acc[i0]);
        float w0 = 1.f / (1.f + e1);
        g_topw[2 * warp]     = w0;
        g_topw[2 * warp + 1] = e1 * w0;
        int p0 = atomicAdd(&g_cnt[i0], 1);
        g_entry[i0 * T_TOK + p0] = warp * 2;
        int p1 = atomicAdd(&g_cnt[i1], 1);
        g_entry[i1 * T_TOK + p1] = warp * 2 + 1;
    }
}

__global__ void aux_kernel(float* out, int has_aux) {
    if (!has_aux) return;
    float s = 0.f;
#pragma unroll
    for (int e = 0; e < NE; e++) { float u = g_usage[e] / (float)T_TOK; s += u * u; }
    out[(size_t)T_TOK * DIM] = (float)NE * s;
}

// ------------------------- conversions (device-resolved destinations) -------------------------
// x -> fp16 hi/lo split
__global__ void conv_x_kernel(const float4* __restrict__ src, int n8) {
    int i = blockIdx.x * blockDim.x + threadIdx.x;
    if (i >= n8) return;
    float4 v0 = src[2 * i], v1 = src[2 * i + 1];
    uint4 h, l;
    split2h(v0.x, v0.y, h.x, l.x);
    split2h(v0.z, v0.w, h.y, l.y);
    split2h(v1.x, v1.y, h.z, l.z);
    split2h(v1.z, v1.w, h.w, l.w);
    ((uint4*)g_xh)[i] = h;
    ((uint4*)g_xl)[i] = l;
}
// weights -> single fp16 (which: 1=w1, 2=w3, 3=w2)
__global__ void conv_w_kernel(const float4* __restrict__ src, int which, int n8) {
    int i = blockIdx.x * blockDim.x + threadIdx.x;
    if (i >= n8) return;
    __half* d;
    switch (which) {
        case 1:  d = g_w1; break;
        case 2:  d = g_w3; break;
        default: d = g_w2; break;
    }
    float4 v0 = src[2 * i], v1 = src[2 * i + 1];
    uint4 h;
    h.x = pack_h2(__float2half_rn(v0.x), __float2half_rn(v0.y));
    h.y = pack_h2(__float2half_rn(v0.z), __float2half_rn(v0.w));
    h.z = pack_h2(__float2half_rn(v1.x), __float2half_rn(v1.y));
    h.w = pack_h2(__float2half_rn(v1.z), __float2half_rn(v1.w));
    ((uint4*)d)[i] = h;
}

// ------------------------- GEMM 1&3 fused over experts -------------------------
// 2-stage, KCH=32 (two k16 sub-tiles). A = x hi/lo fp16, B = w1/w3 single fp16.
// Per k16: C1 += Ah*B1 + Al*B1 ; C3 += Ah*B3 + Al*B3.
#define NCH13 (DIM / KCH)

__global__ __launch_bounds__(256, 2)
void gemm13_mma_kernel()
{
    extern __shared__ uint32_t dynsm[];
    const uint32_t smb = smem_to_u32(dynsm);
    const uint32_t oAh = 0, oAl = 4 * A_ST;
    const uint32_t oB1 = 8 * A_ST, oB3 = 8 * A_ST + 4 * B_ST;

    int e = blockIdx.z;
    int n = g_cnt[e];
    int rowBase = blockIdx.x * 128;
    if (rowBase >= n) return;
    int colBase = blockIdx.y * 64;
    int tid = threadIdx.x, wid = tid >> 5, lane = tid & 31;
    int m0 = (wid & 3) * 32, n0 = (wid >> 2) * 32;
    int grp = lane >> 2, t4 = lane & 3;

    int arow = tid >> 1, ahalf = tid & 1;
    int rA = rowBase + arow;
    int slotA = (rA < n) ? g_entry[e * T_TOK + rA] : 0;
    const __half* srcAh = g_xh + (size_t)(slotA >> 1) * DIM + ahalf * 8;
    const __half* srcAl = g_xl + (size_t)(slotA >> 1) * DIM + ahalf * 8;

    int bidx = tid & 127, bk = bidx >> 3, bseg = bidx & 7;
    int isB3 = tid >> 7;
    const size_t ebW = (size_t)e * DIM * HID;
    const __half* srcB = (isB3 ? g_w3 : g_w1) + ebW + (size_t)bk * HID + colBase + bseg * 8;

    uint32_t dAh[2], dAl[2], dB[2];
#pragma unroll
    for (int st = 0; st < 2; st++) {
        dAh[st] = smb + (oAh + st * 2 * A_ST) * 4 + arow * (PADA * 4) + ahalf * 16;
        dAl[st] = smb + (oAl + st * 2 * A_ST) * 4 + arow * (PADA * 4) + ahalf * 16;
        uint32_t ob = isB3 ? oB3 : oB1;
        dB[st] = smb + (ob + st * 2 * B_ST) * 4 + bk * (PADB * 4) + bseg * 16;
    }

    auto issue = [&](int st) {
#pragma unroll
        for (int sub = 0; sub < 2; sub++) {
            CP16(dAh[st] + sub * A_ST * 4, srcAh + sub * 16);
            CP16(dAl[st] + sub * A_ST * 4, srcAl + sub * 16);
            CP16(dB[st] + sub * B_ST * 4, srcB + (size_t)sub * 16 * HID);
        }
        srcAh += KCH; srcAl += KCH;
        srcB += (size_t)KCH * HID;
    };

    uint32_t loA = lane_offA(lane), loB = lane_offB(lane);
    uint32_t bAH[2], bAL[2], b1B[2], b3B[2];
#pragma unroll
    for (int st = 0; st < 2; st++) {
        bAH[st] = smb + (oAh + st * 2 * A_ST) * 4 + loA + (uint32_t)m0 * (PADA * 4);
        bAL[st] = smb + (oAl + st * 2 * A_ST) * 4 + loA + (uint32_t)m0 * (PADA * 4);
        b1B[st] = smb + (oB1 + st * 2 * B_ST) * 4 + loB + (uint32_t)n0 * 2;
        b3B[st] = smb + (oB3 + st * 2 * B_ST) * 4 + loB + (uint32_t)n0 * 2;
    }

    float c1[2][4][4], c3[2][4][4];
#pragma unroll
    for (int mt = 0; mt < 2; mt++)
#pragma unroll
        for (int j = 0; j < 4; j++)
#pragma unroll
            for (int q = 0; q < 4; q++) { c1[mt][j][q] = 0.f; c3[mt][j][q] = 0.f; }

    issue(0); CP_COMMIT();

    for (int c = 0; c < NCH13; c++) {
        int st = c & 1;
        CP_WAIT0();
        __syncthreads();
        if (c + 1 < NCH13) { issue(st ^ 1); CP_COMMIT(); }
#pragma unroll
        for (int ks = 0; ks < 2; ks++) {
            uint32_t kA = ks * A_ST * 4, kB = ks * B_ST * 4;
            uint32_t ah[2][4], al[2][4];
#pragma unroll
            for (int mt = 0; mt < 2; mt++) {
                ldm_x4(ah[mt], bAH[st] + kA + mt * 16 * (PADA * 4));
                ldm_x4(al[mt], bAL[st] + kA + mt * 16 * (PADA * 4));
            }
#pragma unroll
            for (int nh = 0; nh < 2; nh++) {
                uint32_t f1[4], f3[4];
                ldm_x4_t(f1, b1B[st] + kB + nh * 32);
                ldm_x4_t(f3, b3B[st] + kB + nh * 32);
#pragma unroll
                for (int j = 0; j < 2; j++) {
                    int nt = nh * 2 + j;
                    uint32_t b1F[2] = { f1[2 * j], f1[2 * j + 1] };
                    uint32_t b3F[2] = { f3[2 * j], f3[2 * j + 1] };
#pragma unroll
                    for (int mt = 0; mt < 2; mt++) {
                        mma16816(c1[mt][nt], ah[mt], b1F);
                        mma16816(c1[mt][nt], al[mt], b1F);
                        mma16816(c3[mt][nt], ah[mt], b3F);
                        mma16816(c3[mt][nt], al[mt], b3F);
                    }
                }
            }
        }
    }

    // epilogue: h = silu(c1) * c3 -> fp16 hi/lo at g_Hh/g_Hl[slot]
#pragma unroll
    for (int mt = 0; mt < 2; mt++)
#pragma unroll
        for (int hf = 0; hf < 2; hf++) {
            int rr = m0 + mt * 16 + grp + hf * 8;
            int r = rowBase + rr;
            if (r < n) {
                int slot = g_entry[e * T_TOK + r];
#pragma unroll
                for (int nt = 0; nt < 4; nt++) {
                    int col = colBase + n0 + nt * 8 + t4 * 2;
                    float a0 = c1[mt][nt][hf * 2 + 0], b0 = c3[mt][nt][hf * 2 + 0];
                    float a1 = c1[mt][nt][hf * 2 + 1], b1 = c3[mt][nt][hf * 2 + 1];
                    float h0 = (a0 / (1.f + expf(-a0))) * b0;
                    float h1 = (a1 / (1.f + expf(-a1))) * b1;
                    uint32_t hh, ll;
                    split2h(h0, h1, hh, ll);
                    *(uint32_t*)(g_Hh + (size_t)slot * HID + col) = hh;
                    *(uint32_t*)(g_Hl + (size_t)slot * HID + col) = ll;
                }
            }
        }
}

// ------------------------- GEMM 2 fused over experts -------------------------
// A = H hi/lo fp16, B = w2 single fp16. C += Ah*B + Al*B.
#define NCH2 (HID / KCH)

__global__ __launch_bounds__(256, 2)
void gemm2_mma_kernel(float* __restrict__ out)
{
    extern __shared__ uint32_t dynsm[];
    const uint32_t smb = smem_to_u32(dynsm);
    const uint32_t oAh = 0, oAl = 4 * A_ST;
    const uint32_t oB = 8 * A_ST;
    __shared__ int sSlot[128];

    int e = blockIdx.z;
    int n = g_cnt[e];
    int rowBase = blockIdx.x * 128;
    if (rowBase >= n) return;
    int colBase = blockIdx.y * 64;
    int tid = threadIdx.x, wid = tid >> 5, lane = tid & 31;
    int m0 = (wid & 3) * 32, n0 = (wid >> 2) * 32;
    int grp = lane >> 2, t4 = lane & 3;

    if (tid < 128) {
        int r = rowBase + tid;
        sSlot[tid] = (r < n) ? g_entry[e * T_TOK + r] : 0;
    }
    __syncthreads();

    int arow = tid >> 1, ahalf = tid & 1;
    const __half* srcAh = g_Hh + (size_t)sSlot[arow] * HID + ahalf * 8;
    const __half* srcAl = g_Hl + (size_t)sSlot[arow] * HID + ahalf * 8;

    int bidx = tid & 127, bk = bidx >> 3, bseg = bidx & 7;
    int half2 = tid >> 7;
    const size_t ebW = (size_t)e * HID * DIM;
    const __half* srcB = g_w2 + ebW + (size_t)bk * DIM + colBase + bseg * 8;

    uint32_t dAh[2], dAl[2], dB[2];
#pragma unroll
    for (int st = 0; st < 2; st++) {
        dAh[st] = smb + (oAh + st * 2 * A_ST) * 4 + arow * (PADA * 4) + ahalf * 16;
        dAl[st] = smb + (oAl + st * 2 * A_ST) * 4 + arow * (PADA * 4) + ahalf * 16;
        dB[st] = smb + (oB + st * 2 * B_ST) * 4 + bk * (PADB * 4) + bseg * 16;
    }

    auto issue = [&](int st) {
#pragma unroll
        for (int sub = 0; sub < 2; sub++) {
            CP16(dAh[st] + sub * A_ST * 4, srcAh + sub * 16);
            CP16(dAl[st] + sub * A_ST * 4, srcAl + sub * 16);
            if (!half2)
                CP16(dB[st] + sub * B_ST * 4, srcB + (size_t)sub * 16 * DIM);
        }
        srcAh += KCH; srcAl += KCH;
        srcB += (size_t)KCH * DIM;
    };

    uint32_t loA = lane_offA(lane), loB = lane_offB(lane);
    uint32_t bAH[2], bAL[2], bB[2];
#pragma unroll
    for (int st = 0; st < 2; st++) {
        bAH[st] = smb + (oAh + st * 2 * A_ST) * 4 + loA + (uint32_t)m0 * (PADA * 4);
        bAL[st] = smb + (oAl + st * 2 * A_ST) * 4 + loA + (uint32_t)m0 * (PADA * 4);
        bB[st] = smb + (oB + st * 2 * B_ST) * 4 + loB + (uint32_t)n0 * 2;
    }

    float acc[2][4][4];
#pragma unroll
    for (int mt = 0; mt < 2; mt++)
#pragma unroll
        for (int j = 0; j < 4; j++)
#pragma unroll
            for (int q = 0; q < 4; q++) acc[mt][j][q] = 0.f;

    issue(0); CP_COMMIT();

    for (int c = 0; c < NCH2; c++) {
        int st = c & 1;
        CP_WAIT0();
        __syncthreads();
        if (c + 1 < NCH2) { issue(st ^ 1); CP_COMMIT(); }
#pragma unroll
        for (int ks = 0; ks < 2; ks++) {
            uint32_t kA = ks * A_ST * 4, kB = ks * B_ST * 4;
            uint32_t ah[2][4], al[2][4];
#pragma unroll
            for (int mt = 0; mt < 2; mt++) {
                ldm_x4(ah[mt], bAH[st] + kA + mt * 16 * (PADA * 4));
                ldm_x4(al[mt], bAL[st] + kA + mt * 16 * (PADA * 4));
            }
#pragma unroll
            for (int nh = 0; nh < 2; nh++) {
                uint32_t f[4];
                ldm_x4_t(f, bB[st] + kB + nh * 32);
#pragma unroll
                for (int j = 0; j < 2; j++) {
                    int nt = nh * 2 + j;
                    uint32_t bF[2] = { f[2 * j], f[2 * j + 1] };
#pragma unroll
                    for (int mt = 0; mt < 2; mt++) {
                        mma16816(acc[mt][nt], ah[mt], bF);
                        mma16816(acc[mt][nt], al[mt], bF);
                    }
                }
            }
        }
    }

    // epilogue: atomic combine into out
#pragma unroll
    for (int mt = 0; mt < 2; mt++)
#pragma unroll
        for (int hf = 0; hf < 2; hf++) {
            int rr = m0 + mt * 16 + grp + hf * 8;
            int r = rowBase + rr;
            if (r < n) {
                int slot = sSlot[rr];
                float wgt = g_topw[slot];
                float* op = out + (size_t)(slot >> 1) * DIM;
#pragma unroll
                for (int nt = 0; nt < 4; nt++) {
                    int col = colBase + n0 + nt * 8 + t4 * 2;
                    atomicAdd(op + col,     wgt * acc[mt][nt][hf * 2 + 0]);
                    atomicAdd(op + col + 1, wgt * acc[mt][nt][hf * 2 + 1]);
                }
            }
        }
}

// ------------------------- launch -------------------------
extern "C" void kernel_launch(void* const* d_in, const int* in_sizes, int n_in,
                              void* d_out, int out_size) {
    const float* x  = (const float*)d_in[0];
    const float* gw = (const float*)d_in[1];
    const float* w1 = (const float*)d_in[2];
    const float* w2 = (const float*)d_in[3];
    const float* w3 = (const float*)d_in[4];
    float* out = (float*)d_out;

    const int out_elems = T_TOK * DIM;
    const int out_elems4 = out_elems / 4;
    const int xn8 = T_TOK * DIM / 8;
    const int wn8 = NE * DIM * HID / 8;

    cudaFuncSetAttribute(gemm13_mma_kernel, cudaFuncAttributeMaxDynamicSharedMemorySize, SMEM13_BYTES);
    cudaFuncSetAttribute(gemm2_mma_kernel,  cudaFuncAttributeMaxDynamicSharedMemorySize, SMEM2_BYTES);

    init_kernel<<<(out_elems4 + 255) / 256, 256>>>(out, out_elems4);
    router_kernel<<<T_TOK / 8, 256>>>(x, gw);
    aux_kernel<<<1, 1>>>(out, (out_size > out_elems) ? 1 : 0);

    conv_x_kernel<<<(xn8 + 255) / 256, 256>>>((const float4*)x, xn8);
    conv_w_kernel<<<(wn8 + 255) / 256, 256>>>((const float4*)w1, 1, wn8);
    conv_w_kernel<<<(wn8 + 255) / 256, 256>>>((const float4*)w3, 2, wn8);
    conv_w_kernel<<<(wn8 + 255) / 256, 256>>>((const float4*)w2, 3, wn8);

    gemm13_mma_kernel<<<dim3(T_TOK / 128, HID / 64, NE), 256, SMEM13_BYTES>>>();
    gemm2_mma_kernel<<<dim3(T_TOK / 128, DIM / 64, NE), 256, SMEM2_BYTES>>>(out);
}